// round 16
// baseline (speedup 1.0000x reference)
#include <cuda_runtime.h>
#include <cuda_bf16.h>
#include <math.h>

// Problem constants
#define BB    2
#define LQ_   2048
#define LK_   2048
#define EE    1024
#define HH    16
#define DKK   64
#define DVV   64
#define TOPK_ 64

// Device scratch
__device__ __align__(256) float g_qp[BB*HH*LQ_*DKK];
__device__ __align__(256) float g_kp[BB*HH*LK_*DKK];
__device__ __align__(256) float g_vp[BB*HH*LK_*DVV];
__device__ __align__(256) float g_mix[BB*LQ_*HH*DVV];
__device__ __align__(256) float g_logits[(size_t)BB*HH*LQ_*LK_]; // 512MB

// --------------------------- f32x2 helpers --------------------------------
typedef unsigned long long ull;
__device__ __forceinline__ ull dup2(float x) {
    ull r; asm("mov.b64 %0, {%1, %1};" : "=l"(r) : "f"(x)); return r;
}
__device__ __forceinline__ ull fma2(ull a, ull b, ull c) {
    ull d; asm("fma.rn.f32x2 %0, %1, %2, %3;" : "=l"(d) : "l"(a), "l"(b), "l"(c)); return d;
}
__device__ __forceinline__ float2 unp2(ull p) {
    float2 f; asm("mov.b64 {%0, %1}, %2;" : "=f"(f.x), "=f"(f.y) : "l"(p)); return f;
}

// ---------------------------------------------------------------------------
// Merged projection GEMM: 128x128 tile, 8m x 16n micro, K-tile 16 double-
// buffered (half the syncs of R10's K-tile 8; k-order per output unchanged).
// ---------------------------------------------------------------------------
struct ProjArgs {
    const float* A[3];
    const float* W[3];
    float*       C[3];
    int          K[3];
    float        scale[3];
};

__global__ void __launch_bounds__(128, 2) proj_gemm(ProjArgs pa)
{
    const int z = blockIdx.z;
    const float* __restrict__ A = pa.A[z];
    const float* __restrict__ W = pa.W[z];
    float* __restrict__ C = pa.C[z];
    const int K = pa.K[z];
    const float scale = pa.scale[z];
    const int m0 = blockIdx.y * 128;
    const int n0 = blockIdx.x * 128;
    const int tid = threadIdx.x;
    const int ty = tid >> 3;
    const int tx = tid & 7;

    __shared__ __align__(16) float As[2][16][132];
    __shared__ __align__(16) float Ws[2][16][132];

    ull acc[8][8];
    #pragma unroll
    for (int i = 0; i < 8; i++)
        #pragma unroll
        for (int j = 0; j < 8; j++) acc[i][j] = 0ull;

    const float* Arow = A + (size_t)(m0 + tid) * K;
    const float* Wrow = W + (size_t)(n0 + tid) * K;

    // prologue: stage 0
    #pragma unroll
    for (int s = 0; s < 4; s++) {
        float4 a = *(const float4*)(Arow + s * 4);
        As[0][s*4+0][tid] = a.x; As[0][s*4+1][tid] = a.y;
        As[0][s*4+2][tid] = a.z; As[0][s*4+3][tid] = a.w;
        float4 w = *(const float4*)(Wrow + s * 4);
        Ws[0][s*4+0][tid] = w.x; Ws[0][s*4+1][tid] = w.y;
        Ws[0][s*4+2][tid] = w.z; Ws[0][s*4+3][tid] = w.w;
    }
    __syncthreads();

    const int nT = K >> 4;
    for (int t = 0; t < nT; t++) {
        const int cur = t & 1;
        float4 an[4], wn[4];
        const bool more = (t + 1 < nT);
        if (more) {
            #pragma unroll
            for (int s = 0; s < 4; s++) {
                an[s] = *(const float4*)(Arow + (t + 1) * 16 + s * 4);
                wn[s] = *(const float4*)(Wrow + (t + 1) * 16 + s * 4);
            }
        }
        #pragma unroll
        for (int e = 0; e < 16; e++) {
            float4 a0 = *(const float4*)&As[cur][e][ty * 8];
            float4 a1 = *(const float4*)&As[cur][e][ty * 8 + 4];
            ulonglong2 b0 = *(const ulonglong2*)&Ws[cur][e][tx * 4];
            ulonglong2 b1 = *(const ulonglong2*)&Ws[cur][e][tx * 4 + 32];
            ulonglong2 b2 = *(const ulonglong2*)&Ws[cur][e][tx * 4 + 64];
            ulonglong2 b3 = *(const ulonglong2*)&Ws[cur][e][tx * 4 + 96];
            ull bv[8] = {b0.x, b0.y, b1.x, b1.y, b2.x, b2.y, b3.x, b3.y};
            float av[8] = {a0.x, a0.y, a0.z, a0.w, a1.x, a1.y, a1.z, a1.w};
            #pragma unroll
            for (int i = 0; i < 8; i++) {
                ull ad = dup2(av[i]);
                #pragma unroll
                for (int j = 0; j < 8; j++)
                    acc[i][j] = fma2(ad, bv[j], acc[i][j]);
            }
        }
        if (more) {
            const int nxt = cur ^ 1;
            #pragma unroll
            for (int s = 0; s < 4; s++) {
                As[nxt][s*4+0][tid] = an[s].x; As[nxt][s*4+1][tid] = an[s].y;
                As[nxt][s*4+2][tid] = an[s].z; As[nxt][s*4+3][tid] = an[s].w;
                Ws[nxt][s*4+0][tid] = wn[s].x; Ws[nxt][s*4+1][tid] = wn[s].y;
                Ws[nxt][s*4+2][tid] = wn[s].z; Ws[nxt][s*4+3][tid] = wn[s].w;
            }
            __syncthreads();
        }
    }

    #pragma unroll
    for (int i = 0; i < 8; i++) {
        int m = m0 + ty * 8 + i;
        int b = m >> 11, l = m & 2047;
        #pragma unroll
        for (int c = 0; c < 4; c++) {
            float2 p0 = unp2(acc[i][c*2+0]);
            float2 p1 = unp2(acc[i][c*2+1]);
            float4 o = make_float4(p0.x*scale, p0.y*scale, p1.x*scale, p1.y*scale);
            int n = n0 + tx * 4 + c * 32;
            int h = n >> 6, d = n & 63;
            *(float4*)&C[(((size_t)b * HH + h) * 2048 + l) * 64 + d] = o;
        }
    }
}

// ---------------------------------------------------------------------------
// Logits GEMM, K=64 single-shot (R12, proven).
// ---------------------------------------------------------------------------
__global__ void __launch_bounds__(128, 2) sgemm_logits(
    const float* __restrict__ A0, const float* __restrict__ W0, float* __restrict__ C0,
    size_t sA, size_t sW, size_t sC)
{
    const float* A = A0 + (size_t)blockIdx.z * sA;
    const float* W = W0 + (size_t)blockIdx.z * sW;
    float* C = C0 + (size_t)blockIdx.z * sC;
    const int m0 = blockIdx.y * 128;
    const int n0 = blockIdx.x * 128;
    const int tid = threadIdx.x;
    const int ty = tid >> 3;
    const int tx = tid & 7;
    const int N = LK_;

    __shared__ __align__(16) float As[64][132];
    __shared__ __align__(16) float Ws[64][132];

    {
        const float* Arow = A + (size_t)(m0 + tid) * DKK;
        const float* Wrow = W + (size_t)(n0 + tid) * DKK;
        #pragma unroll
        for (int c4 = 0; c4 < 64; c4 += 4) {
            float4 a = *(const float4*)(Arow + c4);
            As[c4+0][tid] = a.x; As[c4+1][tid] = a.y;
            As[c4+2][tid] = a.z; As[c4+3][tid] = a.w;
            float4 w = *(const float4*)(Wrow + c4);
            Ws[c4+0][tid] = w.x; Ws[c4+1][tid] = w.y;
            Ws[c4+2][tid] = w.z; Ws[c4+3][tid] = w.w;
        }
    }
    __syncthreads();

    ull acc[8][8];
    #pragma unroll
    for (int i = 0; i < 8; i++)
        #pragma unroll
        for (int j = 0; j < 8; j++) acc[i][j] = 0ull;

    #pragma unroll 8
    for (int e = 0; e < 64; e++) {
        float4 a0 = *(const float4*)&As[e][ty * 8];
        float4 a1 = *(const float4*)&As[e][ty * 8 + 4];
        ulonglong2 b0 = *(const ulonglong2*)&Ws[e][tx * 4];
        ulonglong2 b1 = *(const ulonglong2*)&Ws[e][tx * 4 + 32];
        ulonglong2 b2 = *(const ulonglong2*)&Ws[e][tx * 4 + 64];
        ulonglong2 b3 = *(const ulonglong2*)&Ws[e][tx * 4 + 96];
        ull bv[8] = {b0.x, b0.y, b1.x, b1.y, b2.x, b2.y, b3.x, b3.y};
        float av[8] = {a0.x, a0.y, a0.z, a0.w, a1.x, a1.y, a1.z, a1.w};
        #pragma unroll
        for (int i = 0; i < 8; i++) {
            ull ad = dup2(av[i]);
            #pragma unroll
            for (int j = 0; j < 8; j++)
                acc[i][j] = fma2(ad, bv[j], acc[i][j]);
        }
    }

    #pragma unroll
    for (int i = 0; i < 8; i++) {
        int m = m0 + ty * 8 + i;
        #pragma unroll
        for (int c = 0; c < 4; c++) {
            float2 p0 = unp2(acc[i][c*2+0]);
            float2 p1 = unp2(acc[i][c*2+1]);
            float4 o = make_float4(p0.x, p0.y, p1.x, p1.y);
            int n = n0 + tx * 4 + c * 32;
            *(float4*)&C[(size_t)m * N + n] = o;
        }
    }
}

// ---------------------------------------------------------------------------
// fc GEMM: C = A*W^T, N=64, 32-row tiles (grid.y=128). k-seq accumulation.
// ---------------------------------------------------------------------------
__global__ __launch_bounds__(256) void sgemm_fc(
    const float* __restrict__ A, const float* __restrict__ W, float* __restrict__ C,
    int M, int N, int K)
{
    const int m0 = blockIdx.y * 32;
    const int tid = threadIdx.x;
    const int ty = tid >> 4;
    const int tx = tid & 15;

    __shared__ __align__(16) float As[32][36];
    __shared__ __align__(16) float Ws[32][68];

    float acc[2][4];
    #pragma unroll
    for (int i = 0; i < 2; i++)
        #pragma unroll
        for (int j = 0; j < 4; j++) acc[i][j] = 0.f;

    for (int kt = 0; kt < K; kt += 32) {
        {
            int r  = tid >> 3;
            int c4 = (tid & 7) << 2;
            float4 a = *(const float4*)(A + (size_t)(m0 + r) * K + kt + c4);
            As[c4+0][r] = a.x; As[c4+1][r] = a.y; As[c4+2][r] = a.z; As[c4+3][r] = a.w;
        }
        #pragma unroll
        for (int i = 0; i < 2; i++) {
            int f  = tid + i * 256;
            int r  = f >> 3;
            int c4 = (f & 7) << 2;
            float4 w = *(const float4*)(W + (size_t)r * K + kt + c4);
            Ws[c4+0][r] = w.x; Ws[c4+1][r] = w.y; Ws[c4+2][r] = w.z; Ws[c4+3][r] = w.w;
        }
        __syncthreads();
        #pragma unroll
        for (int e = 0; e < 32; e++) {
            float a0 = As[e][ty * 2];
            float a1 = As[e][ty * 2 + 1];
            float4 rb = *(const float4*)&Ws[e][tx << 2];
            float bv[4] = {rb.x, rb.y, rb.z, rb.w};
            #pragma unroll
            for (int j = 0; j < 4; j++) {
                acc[0][j] += a0 * bv[j];
                acc[1][j] += a1 * bv[j];
            }
        }
        __syncthreads();
    }
    #pragma unroll
    for (int i = 0; i < 2; i++) {
        int m = m0 + ty * 2 + i;
        #pragma unroll
        for (int j = 0; j < 4; j++)
            C[(size_t)m * N + (tx << 2) + j] = acc[i][j];
    }
}

// Instrumentation: ncu capture window is launch index 3; keep topk there.
__global__ void noop_kernel() {}

// ---------------------------------------------------------------------------
// Top-k + softmax + sparse AV + attn row write.
// R15 + shortened tail: ONE 8-bit refine pass, then full-key rank-select
// ((value desc, idx asc) = exact jax order) replaces passes 3-4 and finish.
// ---------------------------------------------------------------------------
__device__ __forceinline__ unsigned encf(float x) {
    unsigned u = __float_as_uint(x);
    return (u & 0x80000000u) ? ~u : (u | 0x80000000u);
}
__device__ __forceinline__ float decf(unsigned u) {
    return (u & 0x80000000u) ? __uint_as_float(u ^ 0x80000000u) : __uint_as_float(~u);
}
__device__ __forceinline__ int warp_incl_scan(int v, int lane) {
    #pragma unroll
    for (int o = 1; o < 32; o <<= 1) {
        int n = __shfl_up_sync(0xffffffffu, v, o);
        if (lane >= o) v += n;
    }
    return v;
}
__device__ __forceinline__ int ballot_append(bool flag, int* counter, int lane) {
    unsigned m = __ballot_sync(0xffffffffu, flag);
    int base = 0;
    if (m) {
        int leader = __ffs(m) - 1;
        if (lane == leader) base = atomicAdd(counter, __popc(m));
        base = __shfl_sync(0xffffffffu, base, leader);
    }
    return base + __popc(m & ((1u << lane) - 1u));
}
__device__ __forceinline__ void pick_digit_mw(
    const int wh[4][256], int kk, int tid, int lane, int wid,
    int* wtot, int* s_d, int* s_k)
{
    int b0 = 2 * tid, b1 = 2 * tid + 1;
    int h0 = wh[0][b0] + wh[1][b0] + wh[2][b0] + wh[3][b0];
    int h1 = wh[0][b1] + wh[1][b1] + wh[2][b1] + wh[3][b1];
    int ps = h0 + h1;
    int incl = warp_incl_scan(ps, lane);
    if (lane == 31) wtot[wid] = incl;
    __syncthreads();
    int base = 0;
    #pragma unroll
    for (int w2 = 0; w2 < 4; w2++) if (w2 < wid) base += wtot[w2];
    int Tot = wtot[0] + wtot[1] + wtot[2] + wtot[3];
    int inclAll = incl + base;
    int S0 = Tot - inclAll + ps;
    int S1 = S0 - h0;
    int S2 = S0 - ps;
    if (S0 >= kk && S1 < kk) { *s_d = b0; *s_k = kk - S1; }
    if (S1 >= kk && S2 < kk) { *s_d = b1; *s_k = kk - S2; }
    __syncthreads();
}

__global__ void __launch_bounds__(128, 7) topk_attn_kernel(
    const float* __restrict__ logits, const float* __restrict__ vp,
    float* __restrict__ mix, float* __restrict__ attn, int write_attn)
{
    const int row = blockIdx.x;
    const int bh  = row >> 11;
    const int qi  = row & 2047;
    const int b   = bh >> 4;
    const int h   = bh & 15;
    const int tid = threadIdx.x;
    const int lane = tid & 31;
    const int wid  = tid >> 5;

    __shared__ unsigned su[LK_];
    __shared__ int      cand[LK_];
    __shared__ int      whist[4][256];
    __shared__ int      wtot[4];
    __shared__ unsigned wmax[4];
    __shared__ float    wsum[2];
    __shared__ int      sel_idx[TOPK_];
    __shared__ float    sel_w[TOPK_];
    __shared__ __align__(16) float4 sred4[128];
    __shared__ int      s_d, s_k, s_nsel, s_ncand;
    __shared__ float    s_max, s_invZ;

    // each warp zeros ONLY ITS OWN histogram row; in-warp program order makes
    // the fused hist atomics below race-free, cross-warp reads wait on sync.
    #pragma unroll
    for (int j = 0; j < 8; j++) whist[wid][lane + j * 32] = 0;

    // --- Load + encode + store keys + packed digits + rowmax + hist ---
    const float4* lrow4 = (const float4*)(logits + (size_t)row * LK_);
    unsigned pkd[4];     // 4 digits (top byte) packed per u32
    unsigned lm = 0u;
    #pragma unroll
    for (int it = 0; it < 4; it++) {
        int i4 = tid + it * 128;
        float4 x = __ldcs(lrow4 + i4);
        unsigned e0 = encf(x.x), e1 = encf(x.y), e2 = encf(x.z), e3 = encf(x.w);
        ((uint4*)su)[i4] = make_uint4(e0, e1, e2, e3);
        pkd[it] = (e0 >> 24) | ((e1 >> 24) << 8) | ((e2 >> 24) << 16) | (e3 & 0xff000000u);
        unsigned m01 = e0 > e1 ? e0 : e1;
        unsigned m23 = e2 > e3 ? e2 : e3;
        unsigned m = m01 > m23 ? m01 : m23;
        lm = lm > m ? lm : m;
        unsigned eq[4] = {e0, e1, e2, e3};
        #pragma unroll
        for (int c = 0; c < 4; c++) {
            int dg = (int)(eq[c] >> 24);
            unsigned mm = __match_any_sync(0xffffffffu, dg);
            if ((int)(__ffs(mm) - 1) == lane) atomicAdd(&whist[wid][dg], __popc(mm));
        }
    }
    #pragma unroll
    for (int o = 16; o > 0; o >>= 1) {
        unsigned v = __shfl_xor_sync(0xffffffffu, lm, o);
        lm = lm > v ? lm : v;
    }
    if (lane == 0) wmax[wid] = lm;
    __syncthreads();
    if (tid == 0) {
        unsigned m = wmax[0];
        m = m > wmax[1] ? m : wmax[1];
        m = m > wmax[2] ? m : wmax[2];
        m = m > wmax[3] ? m : wmax[3];
        s_max = decf(m);
    }
    pick_digit_mw(whist, TOPK_, tid, lane, wid, wtot, &s_d, &s_k);
    const float rowmax = s_max;
    const int d1 = s_d;
    int kk = s_k;

    // --- Order-free compaction: SIMD byte counts + one block scan ---
    {
        const unsigned d1x4 = 0x01010101u * (unsigned)d1;
        int cg = 0, ce = 0;
        #pragma unroll
        for (int it = 0; it < 4; it++) {
            cg += __popc(__vcmpgtu4(pkd[it], d1x4));
            ce += __popc(__vcmpeq4(pkd[it], d1x4));
        }
        cg >>= 3; ce >>= 3;
        int packed = (cg << 16) | ce;
        int incl = warp_incl_scan(packed, lane);
        if (lane == 31) wtot[wid] = incl;
        __syncthreads();
        int base = 0, Tot = 0;
        #pragma unroll
        for (int w2 = 0; w2 < 4; w2++) { int v = wtot[w2]; if (w2 < wid) base += v; Tot += v; }
        int excl = incl - packed + base;
        int gp = excl >> 16;
        int ep = excl & 0xffff;
        if (tid == 0) { s_nsel = Tot >> 16; s_ncand = Tot & 0xffff; }
        #pragma unroll
        for (int it = 0; it < 4; it++) {
            unsigned pk = pkd[it];
            #pragma unroll
            for (int c = 0; c < 4; c++) {
                int dg = (int)((pk >> (8 * c)) & 255u);
                int i = 4 * tid + 512 * it + c;
                if (dg > d1)       sel_idx[gp++] = i;
                else if (dg == d1) cand[ep++]    = i;
            }
        }
    }
    __syncthreads();
    int C = s_ncand;

    // --- ONE 8-bit refine pass at shift=16 (if needed) ---
    if (C > kk) {
        #pragma unroll
        for (int j = 0; j < 8; j++) whist[wid][lane + j * 32] = 0;
        __syncthreads();
        for (int c = tid; c < C; c += 128)
            atomicAdd(&whist[wid][(su[cand[c]] >> 16) & 255u], 1);
        __syncthreads();
        pick_digit_mw(whist, kk, tid, lane, wid, wtot, &s_d, &s_k);
        int d = s_d;
        int mine[16]; int nm = 0;
        for (int c = tid; c < C; c += 128) mine[nm++] = cand[c];
        __syncthreads();
        if (tid == 0) s_ncand = 0;
        __syncthreads();
        int Cpad = (C + 127) & ~127;
        int used = 0;
        for (int c0 = 0; c0 < Cpad; c0 += 128) {
            int c = c0 + tid;
            bool active = (c < C);
            int idx = active ? mine[used] : 0;
            if (active) used++;
            int dg = active ? (int)((su[idx] >> 16) & 255u) : -1;
            bool is_g = active && (dg > d);
            bool is_e = active && (dg == d);
            int pg = ballot_append(is_g, &s_nsel, lane);
            if (is_g) sel_idx[pg] = idx;
            int pe = ballot_append(is_e, &s_ncand, lane);
            if (is_e) cand[pe] = idx;
        }
        __syncthreads();
        C = s_ncand;
        kk = s_k;
    }

    // --- Final: full-key rank-select, rank = #{j: (kj>ki) or (kj==ki & idxj<idxi)}
    //     == exact jax (value desc, index asc) order among remaining candidates.
    if (C == kk) {
        for (int c = tid; c < C; c += 128) {
            int pos = atomicAdd(&s_nsel, 1);
            sel_idx[pos] = cand[c];
        }
    } else {
        for (int c = tid; c < C; c += 128) {
            int idx = cand[c];
            unsigned key = su[idx];
            int r = 0;
            for (int j = 0; j < C; j++) {
                int ij = cand[j];
                unsigned k2 = su[ij];
                r += (k2 > key) || (k2 == key && ij < idx);
            }
            if (r < kk) { int pos = atomicAdd(&s_nsel, 1); sel_idx[pos] = idx; }
        }
    }
    __syncthreads();

    // --- Softmax over the 64 selected ---
    float w = 0.f;
    if (tid < TOPK_) {
        w = expf(decf(su[sel_idx[tid]]) - rowmax);
        sel_w[tid] = w;
    }
    float zl = w;
    #pragma unroll
    for (int o = 16; o > 0; o >>= 1) zl += __shfl_xor_sync(0xffffffffu, zl, o);
    if (tid < TOPK_ && lane == 0) wsum[wid] = zl;
    __syncthreads();
    if (tid == 0) s_invZ = 1.0f / (wsum[0] + wsum[1]);
    __syncthreads();
    const float invZ = s_invZ;
    if (tid < TOPK_) sel_w[tid] = sel_w[tid] * invZ;
    __syncthreads();

    // --- Build full attn row in smem (su reused) and stream out ---
    if (write_attn) {
        float4* s4 = (float4*)su;
        const float4 z4 = make_float4(0.f, 0.f, 0.f, 0.f);
        #pragma unroll
        for (int it = 0; it < 4; it++) s4[tid + it * 128] = z4;
        __syncthreads();
        if (tid < TOPK_) ((float*)su)[sel_idx[tid]] = sel_w[tid];
        __syncthreads();
        float4* arow4 = (float4*)(attn + (size_t)row * LK_);
        #pragma unroll
        for (int it = 0; it < 4; it++)
            __stcs(arow4 + tid + it * 128, s4[tid + it * 128]);
    }

    // --- Sparse AV (vectorized: float4 gathers, fixed slice order) ---
    {
        const int dd = (tid & 15) * 4;
        const int sl = tid >> 4;
        const float* vb = vp + (size_t)bh * LK_ * 64;
        float4 accv = make_float4(0.f, 0.f, 0.f, 0.f);
        #pragma unroll
        for (int s = 0; s < 8; s++) {
            int si = sl * 8 + s;
            float ws = sel_w[si];
            float4 v4 = *(const float4*)(vb + (size_t)sel_idx[si] * 64 + dd);
            accv.x += ws * v4.x; accv.y += ws * v4.y;
            accv.z += ws * v4.z; accv.w += ws * v4.w;
        }
        sred4[tid] = accv;
        __syncthreads();
        if (tid < 16) {
            float4 t = make_float4(0.f, 0.f, 0.f, 0.f);
            #pragma unroll
            for (int s = 0; s < 8; s++) {
                float4 v = sred4[s * 16 + tid];
                t.x += v.x; t.y += v.y; t.z += v.z; t.w += v.w;
            }
            *(float4*)&mix[((size_t)(b * LQ_ + qi)) * (HH * DVV) + h * 64 + tid * 4] = t;
        }
    }
}

// ---------------------------------------------------------------------------
extern "C" void kernel_launch(void* const* d_in, const int* in_sizes, int n_in,
                              void* d_out, int out_size) {
    (void)in_sizes; (void)n_in;
    const float* q    = (const float*)d_in[0];
    const float* k    = (const float*)d_in[1];
    const float* v    = (const float*)d_in[2];
    const float* w_qs = (const float*)d_in[3];
    const float* w_ks = (const float*)d_in[4];
    const float* w_vs = (const float*)d_in[5];
    const float* fc   = (const float*)d_in[6];
    float* out = (float*)d_out;

    float *qp, *kp, *vp, *mix, *lg;
    cudaGetSymbolAddress((void**)&qp,  g_qp);
    cudaGetSymbolAddress((void**)&kp,  g_kp);
    cudaGetSymbolAddress((void**)&vp,  g_vp);
    cudaGetSymbolAddress((void**)&mix, g_mix);
    cudaGetSymbolAddress((void**)&lg,  g_logits);

    const long long out_elems  = (long long)BB * LQ_ * DVV;           // 262144
    const long long attn_elems = (long long)BB * HH * LQ_ * LK_;      // 134217728
    int write_attn = ((long long)out_size >= out_elems + attn_elems) ? 1 : 0;
    float* attn = out + out_elems;

    // launch 0: merged QP/KP/VP projections (z-batched, K-tile 16)
    ProjArgs pa;
    pa.A[0] = q;    pa.W[0] = w_qs; pa.C[0] = qp; pa.K[0] = EE;  pa.scale[0] = 0.125f;
    pa.A[1] = k;    pa.W[1] = w_ks; pa.C[1] = kp; pa.K[1] = EE;  pa.scale[1] = 1.0f;
    pa.A[2] = v;    pa.W[2] = w_vs; pa.C[2] = vp; pa.K[2] = DVV; pa.scale[2] = 1.0f;
    proj_gemm<<<dim3(8, 32, 3), 128>>>(pa);

    // launch 1: logits[bh] = QP[bh] @ KP[bh]^T (K=64 single-shot smem)
    sgemm_logits<<<dim3(16, 16, BB*HH), 128>>>(qp, kp, lg,
                                               (size_t)LQ_ * DKK, (size_t)LK_ * DKK,
                                               (size_t)LQ_ * LK_);

    // launch 2: noop so the ncu capture window (index 3) lands on topk
    noop_kernel<<<1, 32>>>();

    // launch 3: top-k + softmax + AV + attn   <-- ncu window
    topk_attn_kernel<<<BB * HH * LQ_, 128>>>(lg, vp, mix, attn, write_attn);

    // launch 4: out = mix @ fc^T
    sgemm_fc<<<dim3(1, 128), 256>>>(mix, fc, out, BB*LQ_, DVV, HH*DVV);
}

// round 17
// speedup vs baseline: 1.0338x; 1.0338x over previous
#include <cuda_runtime.h>
#include <cuda_bf16.h>
#include <math.h>

// Problem constants
#define BB    2
#define LQ_   2048
#define LK_   2048
#define EE    1024
#define HH    16
#define DKK   64
#define DVV   64
#define TOPK_ 64

// Device scratch
__device__ __align__(256) float g_qp[BB*HH*LQ_*DKK];
__device__ __align__(256) float g_kp[BB*HH*LK_*DKK];
__device__ __align__(256) float g_vp[BB*HH*LK_*DVV];
__device__ __align__(256) float g_mix[BB*LQ_*HH*DVV];
__device__ __align__(256) float g_logits[(size_t)BB*HH*LQ_*LK_]; // 512MB

// --------------------------- f32x2 helpers --------------------------------
typedef unsigned long long ull;
__device__ __forceinline__ ull dup2(float x) {
    ull r; asm("mov.b64 %0, {%1, %1};" : "=l"(r) : "f"(x)); return r;
}
__device__ __forceinline__ ull fma2(ull a, ull b, ull c) {
    ull d; asm("fma.rn.f32x2 %0, %1, %2, %3;" : "=l"(d) : "l"(a), "l"(b), "l"(c)); return d;
}
__device__ __forceinline__ float2 unp2(ull p) {
    float2 f; asm("mov.b64 {%0, %1}, %2;" : "=f"(f.x), "=f"(f.y) : "l"(p)); return f;
}

// ---------------------------------------------------------------------------
// Merged projection GEMM (R10/R15 proven core): 128x128 tile, 8m x 16n micro,
// K-tile 8 double-buffered, 128 threads, f32x2 FMA, B in 4 chunks stride 32.
// ---------------------------------------------------------------------------
struct ProjArgs {
    const float* A[3];
    const float* W[3];
    float*       C[3];
    int          K[3];
    float        scale[3];
};

__global__ void __launch_bounds__(128, 2) proj_gemm(ProjArgs pa)
{
    const int z = blockIdx.z;
    const float* __restrict__ A = pa.A[z];
    const float* __restrict__ W = pa.W[z];
    float* __restrict__ C = pa.C[z];
    const int K = pa.K[z];
    const float scale = pa.scale[z];
    const int m0 = blockIdx.y * 128;
    const int n0 = blockIdx.x * 128;
    const int tid = threadIdx.x;
    const int ty = tid >> 3;
    const int tx = tid & 7;

    __shared__ __align__(16) float As[2][8][132];
    __shared__ __align__(16) float Ws[2][8][132];

    ull acc[8][8];
    #pragma unroll
    for (int i = 0; i < 8; i++)
        #pragma unroll
        for (int j = 0; j < 8; j++) acc[i][j] = 0ull;

    const float* Arow = A + (size_t)(m0 + tid) * K;
    const float* Wrow = W + (size_t)(n0 + tid) * K;
    {
        float4 a0 = *(const float4*)(Arow);
        float4 a1 = *(const float4*)(Arow + 4);
        float4 w0 = *(const float4*)(Wrow);
        float4 w1 = *(const float4*)(Wrow + 4);
        As[0][0][tid]=a0.x; As[0][1][tid]=a0.y; As[0][2][tid]=a0.z; As[0][3][tid]=a0.w;
        As[0][4][tid]=a1.x; As[0][5][tid]=a1.y; As[0][6][tid]=a1.z; As[0][7][tid]=a1.w;
        Ws[0][0][tid]=w0.x; Ws[0][1][tid]=w0.y; Ws[0][2][tid]=w0.z; Ws[0][3][tid]=w0.w;
        Ws[0][4][tid]=w1.x; Ws[0][5][tid]=w1.y; Ws[0][6][tid]=w1.z; Ws[0][7][tid]=w1.w;
    }
    __syncthreads();

    const int nT = K >> 3;
    for (int t = 0; t < nT; t++) {
        const int cur = t & 1;
        float4 an0, an1, wn0, wn1;
        const bool more = (t + 1 < nT);
        if (more) {
            an0 = *(const float4*)(Arow + (t + 1) * 8);
            an1 = *(const float4*)(Arow + (t + 1) * 8 + 4);
            wn0 = *(const float4*)(Wrow + (t + 1) * 8);
            wn1 = *(const float4*)(Wrow + (t + 1) * 8 + 4);
        }
        #pragma unroll
        for (int e = 0; e < 8; e++) {
            float4 a0 = *(const float4*)&As[cur][e][ty * 8];
            float4 a1 = *(const float4*)&As[cur][e][ty * 8 + 4];
            ulonglong2 b0 = *(const ulonglong2*)&Ws[cur][e][tx * 4];
            ulonglong2 b1 = *(const ulonglong2*)&Ws[cur][e][tx * 4 + 32];
            ulonglong2 b2 = *(const ulonglong2*)&Ws[cur][e][tx * 4 + 64];
            ulonglong2 b3 = *(const ulonglong2*)&Ws[cur][e][tx * 4 + 96];
            ull bv[8] = {b0.x, b0.y, b1.x, b1.y, b2.x, b2.y, b3.x, b3.y};
            float av[8] = {a0.x, a0.y, a0.z, a0.w, a1.x, a1.y, a1.z, a1.w};
            #pragma unroll
            for (int i = 0; i < 8; i++) {
                ull ad = dup2(av[i]);
                #pragma unroll
                for (int j = 0; j < 8; j++)
                    acc[i][j] = fma2(ad, bv[j], acc[i][j]);
            }
        }
        if (more) {
            const int nxt = cur ^ 1;
            As[nxt][0][tid]=an0.x; As[nxt][1][tid]=an0.y; As[nxt][2][tid]=an0.z; As[nxt][3][tid]=an0.w;
            As[nxt][4][tid]=an1.x; As[nxt][5][tid]=an1.y; As[nxt][6][tid]=an1.z; As[nxt][7][tid]=an1.w;
            Ws[nxt][0][tid]=wn0.x; Ws[nxt][1][tid]=wn0.y; Ws[nxt][2][tid]=wn0.z; Ws[nxt][3][tid]=wn0.w;
            Ws[nxt][4][tid]=wn1.x; Ws[nxt][5][tid]=wn1.y; Ws[nxt][6][tid]=wn1.z; Ws[nxt][7][tid]=wn1.w;
            __syncthreads();
        }
    }

    #pragma unroll
    for (int i = 0; i < 8; i++) {
        int m = m0 + ty * 8 + i;
        int b = m >> 11, l = m & 2047;
        #pragma unroll
        for (int c = 0; c < 4; c++) {
            float2 p0 = unp2(acc[i][c*2+0]);
            float2 p1 = unp2(acc[i][c*2+1]);
            float4 o = make_float4(p0.x*scale, p0.y*scale, p1.x*scale, p1.y*scale);
            int n = n0 + tx * 4 + c * 32;
            int h = n >> 6, d = n & 63;
            *(float4*)&C[(((size_t)b * HH + h) * 2048 + l) * 64 + d] = o;
        }
    }
}

// ---------------------------------------------------------------------------
// Logits GEMM, K=64 single-shot (R12, proven).
// ---------------------------------------------------------------------------
__global__ void __launch_bounds__(128, 2) sgemm_logits(
    const float* __restrict__ A0, const float* __restrict__ W0, float* __restrict__ C0,
    size_t sA, size_t sW, size_t sC)
{
    const float* A = A0 + (size_t)blockIdx.z * sA;
    const float* W = W0 + (size_t)blockIdx.z * sW;
    float* C = C0 + (size_t)blockIdx.z * sC;
    const int m0 = blockIdx.y * 128;
    const int n0 = blockIdx.x * 128;
    const int tid = threadIdx.x;
    const int ty = tid >> 3;
    const int tx = tid & 7;
    const int N = LK_;

    __shared__ __align__(16) float As[64][132];
    __shared__ __align__(16) float Ws[64][132];

    {
        const float* Arow = A + (size_t)(m0 + tid) * DKK;
        const float* Wrow = W + (size_t)(n0 + tid) * DKK;
        #pragma unroll
        for (int c4 = 0; c4 < 64; c4 += 4) {
            float4 a = *(const float4*)(Arow + c4);
            As[c4+0][tid] = a.x; As[c4+1][tid] = a.y;
            As[c4+2][tid] = a.z; As[c4+3][tid] = a.w;
            float4 w = *(const float4*)(Wrow + c4);
            Ws[c4+0][tid] = w.x; Ws[c4+1][tid] = w.y;
            Ws[c4+2][tid] = w.z; Ws[c4+3][tid] = w.w;
        }
    }
    __syncthreads();

    ull acc[8][8];
    #pragma unroll
    for (int i = 0; i < 8; i++)
        #pragma unroll
        for (int j = 0; j < 8; j++) acc[i][j] = 0ull;

    #pragma unroll 8
    for (int e = 0; e < 64; e++) {
        float4 a0 = *(const float4*)&As[e][ty * 8];
        float4 a1 = *(const float4*)&As[e][ty * 8 + 4];
        ulonglong2 b0 = *(const ulonglong2*)&Ws[e][tx * 4];
        ulonglong2 b1 = *(const ulonglong2*)&Ws[e][tx * 4 + 32];
        ulonglong2 b2 = *(const ulonglong2*)&Ws[e][tx * 4 + 64];
        ulonglong2 b3 = *(const ulonglong2*)&Ws[e][tx * 4 + 96];
        ull bv[8] = {b0.x, b0.y, b1.x, b1.y, b2.x, b2.y, b3.x, b3.y};
        float av[8] = {a0.x, a0.y, a0.z, a0.w, a1.x, a1.y, a1.z, a1.w};
        #pragma unroll
        for (int i = 0; i < 8; i++) {
            ull ad = dup2(av[i]);
            #pragma unroll
            for (int j = 0; j < 8; j++)
                acc[i][j] = fma2(ad, bv[j], acc[i][j]);
        }
    }

    #pragma unroll
    for (int i = 0; i < 8; i++) {
        int m = m0 + ty * 8 + i;
        #pragma unroll
        for (int c = 0; c < 4; c++) {
            float2 p0 = unp2(acc[i][c*2+0]);
            float2 p1 = unp2(acc[i][c*2+1]);
            float4 o = make_float4(p0.x, p0.y, p1.x, p1.y);
            int n = n0 + tx * 4 + c * 32;
            *(float4*)&C[(size_t)m * N + n] = o;
        }
    }
}

// ---------------------------------------------------------------------------
// fc GEMM: C = A*W^T, N=64, 32-row tiles (grid.y=128). k-seq accumulation.
// ---------------------------------------------------------------------------
__global__ __launch_bounds__(256) void sgemm_fc(
    const float* __restrict__ A, const float* __restrict__ W, float* __restrict__ C,
    int M, int N, int K)
{
    const int m0 = blockIdx.y * 32;
    const int tid = threadIdx.x;
    const int ty = tid >> 4;
    const int tx = tid & 15;

    __shared__ __align__(16) float As[32][36];
    __shared__ __align__(16) float Ws[32][68];

    float acc[2][4];
    #pragma unroll
    for (int i = 0; i < 2; i++)
        #pragma unroll
        for (int j = 0; j < 4; j++) acc[i][j] = 0.f;

    for (int kt = 0; kt < K; kt += 32) {
        {
            int r  = tid >> 3;
            int c4 = (tid & 7) << 2;
            float4 a = *(const float4*)(A + (size_t)(m0 + r) * K + kt + c4);
            As[c4+0][r] = a.x; As[c4+1][r] = a.y; As[c4+2][r] = a.z; As[c4+3][r] = a.w;
        }
        #pragma unroll
        for (int i = 0; i < 2; i++) {
            int f  = tid + i * 256;
            int r  = f >> 3;
            int c4 = (f & 7) << 2;
            float4 w = *(const float4*)(W + (size_t)r * K + kt + c4);
            Ws[c4+0][r] = w.x; Ws[c4+1][r] = w.y; Ws[c4+2][r] = w.z; Ws[c4+3][r] = w.w;
        }
        __syncthreads();
        #pragma unroll
        for (int e = 0; e < 32; e++) {
            float a0 = As[e][ty * 2];
            float a1 = As[e][ty * 2 + 1];
            float4 rb = *(const float4*)&Ws[e][tx << 2];
            float bv[4] = {rb.x, rb.y, rb.z, rb.w};
            #pragma unroll
            for (int j = 0; j < 4; j++) {
                acc[0][j] += a0 * bv[j];
                acc[1][j] += a1 * bv[j];
            }
        }
        __syncthreads();
    }
    #pragma unroll
    for (int i = 0; i < 2; i++) {
        int m = m0 + ty * 2 + i;
        #pragma unroll
        for (int j = 0; j < 4; j++)
            C[(size_t)m * N + (tx << 2) + j] = acc[i][j];
    }
}

// Instrumentation: ncu capture window is launch index 3; keep topk there.
__global__ void noop_kernel() {}

// ---------------------------------------------------------------------------
// Top-k + softmax + sparse AV + attn row write (R16 topk, proven 447us).
// ---------------------------------------------------------------------------
__device__ __forceinline__ unsigned encf(float x) {
    unsigned u = __float_as_uint(x);
    return (u & 0x80000000u) ? ~u : (u | 0x80000000u);
}
__device__ __forceinline__ float decf(unsigned u) {
    return (u & 0x80000000u) ? __uint_as_float(u ^ 0x80000000u) : __uint_as_float(~u);
}
__device__ __forceinline__ int warp_incl_scan(int v, int lane) {
    #pragma unroll
    for (int o = 1; o < 32; o <<= 1) {
        int n = __shfl_up_sync(0xffffffffu, v, o);
        if (lane >= o) v += n;
    }
    return v;
}
__device__ __forceinline__ int ballot_append(bool flag, int* counter, int lane) {
    unsigned m = __ballot_sync(0xffffffffu, flag);
    int base = 0;
    if (m) {
        int leader = __ffs(m) - 1;
        if (lane == leader) base = atomicAdd(counter, __popc(m));
        base = __shfl_sync(0xffffffffu, base, leader);
    }
    return base + __popc(m & ((1u << lane) - 1u));
}
__device__ __forceinline__ void pick_digit_mw(
    const int wh[4][256], int kk, int tid, int lane, int wid,
    int* wtot, int* s_d, int* s_k)
{
    int b0 = 2 * tid, b1 = 2 * tid + 1;
    int h0 = wh[0][b0] + wh[1][b0] + wh[2][b0] + wh[3][b0];
    int h1 = wh[0][b1] + wh[1][b1] + wh[2][b1] + wh[3][b1];
    int ps = h0 + h1;
    int incl = warp_incl_scan(ps, lane);
    if (lane == 31) wtot[wid] = incl;
    __syncthreads();
    int base = 0;
    #pragma unroll
    for (int w2 = 0; w2 < 4; w2++) if (w2 < wid) base += wtot[w2];
    int Tot = wtot[0] + wtot[1] + wtot[2] + wtot[3];
    int inclAll = incl + base;
    int S0 = Tot - inclAll + ps;
    int S1 = S0 - h0;
    int S2 = S0 - ps;
    if (S0 >= kk && S1 < kk) { *s_d = b0; *s_k = kk - S1; }
    if (S1 >= kk && S2 < kk) { *s_d = b1; *s_k = kk - S2; }
    __syncthreads();
}

__global__ void __launch_bounds__(128, 7) topk_attn_kernel(
    const float* __restrict__ logits, const float* __restrict__ vp,
    float* __restrict__ mix, float* __restrict__ attn, int write_attn)
{
    const int row = blockIdx.x;
    const int bh  = row >> 11;
    const int qi  = row & 2047;
    const int b   = bh >> 4;
    const int h   = bh & 15;
    const int tid = threadIdx.x;
    const int lane = tid & 31;
    const int wid  = tid >> 5;

    __shared__ unsigned su[LK_];
    __shared__ int      cand[LK_];
    __shared__ int      whist[4][256];
    __shared__ int      wtot[4];
    __shared__ unsigned wmax[4];
    __shared__ float    wsum[2];
    __shared__ int      sel_idx[TOPK_];
    __shared__ float    sel_w[TOPK_];
    __shared__ __align__(16) float4 sred4[128];
    __shared__ int      s_d, s_k, s_nsel, s_ncand;
    __shared__ float    s_max, s_invZ;

    // each warp zeros ONLY ITS OWN histogram row; in-warp program order makes
    // the fused hist atomics below race-free, cross-warp reads wait on sync.
    #pragma unroll
    for (int j = 0; j < 8; j++) whist[wid][lane + j * 32] = 0;

    // --- Load + encode + store keys + packed digits + rowmax + hist ---
    const float4* lrow4 = (const float4*)(logits + (size_t)row * LK_);
    unsigned pkd[4];     // 4 digits (top byte) packed per u32
    unsigned lm = 0u;
    #pragma unroll
    for (int it = 0; it < 4; it++) {
        int i4 = tid + it * 128;
        float4 x = __ldcs(lrow4 + i4);
        unsigned e0 = encf(x.x), e1 = encf(x.y), e2 = encf(x.z), e3 = encf(x.w);
        ((uint4*)su)[i4] = make_uint4(e0, e1, e2, e3);
        pkd[it] = (e0 >> 24) | ((e1 >> 24) << 8) | ((e2 >> 24) << 16) | (e3 & 0xff000000u);
        unsigned m01 = e0 > e1 ? e0 : e1;
        unsigned m23 = e2 > e3 ? e2 : e3;
        unsigned m = m01 > m23 ? m01 : m23;
        lm = lm > m ? lm : m;
        unsigned eq[4] = {e0, e1, e2, e3};
        #pragma unroll
        for (int c = 0; c < 4; c++) {
            int dg = (int)(eq[c] >> 24);
            unsigned mm = __match_any_sync(0xffffffffu, dg);
            if ((int)(__ffs(mm) - 1) == lane) atomicAdd(&whist[wid][dg], __popc(mm));
        }
    }
    #pragma unroll
    for (int o = 16; o > 0; o >>= 1) {
        unsigned v = __shfl_xor_sync(0xffffffffu, lm, o);
        lm = lm > v ? lm : v;
    }
    if (lane == 0) wmax[wid] = lm;
    __syncthreads();
    if (tid == 0) {
        unsigned m = wmax[0];
        m = m > wmax[1] ? m : wmax[1];
        m = m > wmax[2] ? m : wmax[2];
        m = m > wmax[3] ? m : wmax[3];
        s_max = decf(m);
    }
    pick_digit_mw(whist, TOPK_, tid, lane, wid, wtot, &s_d, &s_k);
    const float rowmax = s_max;
    const int d1 = s_d;
    int kk = s_k;

    // --- Order-free compaction: SIMD byte counts + one block scan ---
    {
        const unsigned d1x4 = 0x01010101u * (unsigned)d1;
        int cg = 0, ce = 0;
        #pragma unroll
        for (int it = 0; it < 4; it++) {
            cg += __popc(__vcmpgtu4(pkd[it], d1x4));
            ce += __popc(__vcmpeq4(pkd[it], d1x4));
        }
        cg >>= 3; ce >>= 3;
        int packed = (cg << 16) | ce;
        int incl = warp_incl_scan(packed, lane);
        if (lane == 31) wtot[wid] = incl;
        __syncthreads();
        int base = 0, Tot = 0;
        #pragma unroll
        for (int w2 = 0; w2 < 4; w2++) { int v = wtot[w2]; if (w2 < wid) base += v; Tot += v; }
        int excl = incl - packed + base;
        int gp = excl >> 16;
        int ep = excl & 0xffff;
        if (tid == 0) { s_nsel = Tot >> 16; s_ncand = Tot & 0xffff; }
        #pragma unroll
        for (int it = 0; it < 4; it++) {
            unsigned pk = pkd[it];
            #pragma unroll
            for (int c = 0; c < 4; c++) {
                int dg = (int)((pk >> (8 * c)) & 255u);
                int i = 4 * tid + 512 * it + c;
                if (dg > d1)       sel_idx[gp++] = i;
                else if (dg == d1) cand[ep++]    = i;
            }
        }
    }
    __syncthreads();
    int C = s_ncand;

    // --- ONE 8-bit refine pass at shift=16 (if needed) ---
    if (C > kk) {
        #pragma unroll
        for (int j = 0; j < 8; j++) whist[wid][lane + j * 32] = 0;
        __syncthreads();
        for (int c = tid; c < C; c += 128)
            atomicAdd(&whist[wid][(su[cand[c]] >> 16) & 255u], 1);
        __syncthreads();
        pick_digit_mw(whist, kk, tid, lane, wid, wtot, &s_d, &s_k);
        int d = s_d;
        int mine[16]; int nm = 0;
        for (int c = tid; c < C; c += 128) mine[nm++] = cand[c];
        __syncthreads();
        if (tid == 0) s_ncand = 0;
        __syncthreads();
        int Cpad = (C + 127) & ~127;
        int used = 0;
        for (int c0 = 0; c0 < Cpad; c0 += 128) {
            int c = c0 + tid;
            bool active = (c < C);
            int idx = active ? mine[used] : 0;
            if (active) used++;
            int dg = active ? (int)((su[idx] >> 16) & 255u) : -1;
            bool is_g = active && (dg > d);
            bool is_e = active && (dg == d);
            int pg = ballot_append(is_g, &s_nsel, lane);
            if (is_g) sel_idx[pg] = idx;
            int pe = ballot_append(is_e, &s_ncand, lane);
            if (is_e) cand[pe] = idx;
        }
        __syncthreads();
        C = s_ncand;
        kk = s_k;
    }

    // --- Final: full-key rank-select (== jax (value desc, idx asc) order) ---
    if (C == kk) {
        for (int c = tid; c < C; c += 128) {
            int pos = atomicAdd(&s_nsel, 1);
            sel_idx[pos] = cand[c];
        }
    } else {
        for (int c = tid; c < C; c += 128) {
            int idx = cand[c];
            unsigned key = su[idx];
            int r = 0;
            for (int j = 0; j < C; j++) {
                int ij = cand[j];
                unsigned k2 = su[ij];
                r += (k2 > key) || (k2 == key && ij < idx);
            }
            if (r < kk) { int pos = atomicAdd(&s_nsel, 1); sel_idx[pos] = idx; }
        }
    }
    __syncthreads();

    // --- Softmax over the 64 selected ---
    float w = 0.f;
    if (tid < TOPK_) {
        w = expf(decf(su[sel_idx[tid]]) - rowmax);
        sel_w[tid] = w;
    }
    float zl = w;
    #pragma unroll
    for (int o = 16; o > 0; o >>= 1) zl += __shfl_xor_sync(0xffffffffu, zl, o);
    if (tid < TOPK_ && lane == 0) wsum[wid] = zl;
    __syncthreads();
    if (tid == 0) s_invZ = 1.0f / (wsum[0] + wsum[1]);
    __syncthreads();
    const float invZ = s_invZ;
    if (tid < TOPK_) sel_w[tid] = sel_w[tid] * invZ;
    __syncthreads();

    // --- Build full attn row in smem (su reused) and stream out ---
    if (write_attn) {
        float4* s4 = (float4*)su;
        const float4 z4 = make_float4(0.f, 0.f, 0.f, 0.f);
        #pragma unroll
        for (int it = 0; it < 4; it++) s4[tid + it * 128] = z4;
        __syncthreads();
        if (tid < TOPK_) ((float*)su)[sel_idx[tid]] = sel_w[tid];
        __syncthreads();
        float4* arow4 = (float4*)(attn + (size_t)row * LK_);
        #pragma unroll
        for (int it = 0; it < 4; it++)
            __stcs(arow4 + tid + it * 128, s4[tid + it * 128]);
    }

    // --- Sparse AV (vectorized: float4 gathers, fixed slice order) ---
    {
        const int dd = (tid & 15) * 4;
        const int sl = tid >> 4;
        const float* vb = vp + (size_t)bh * LK_ * 64;
        float4 accv = make_float4(0.f, 0.f, 0.f, 0.f);
        #pragma unroll
        for (int s = 0; s < 8; s++) {
            int si = sl * 8 + s;
            float ws = sel_w[si];
            float4 v4 = *(const float4*)(vb + (size_t)sel_idx[si] * 64 + dd);
            accv.x += ws * v4.x; accv.y += ws * v4.y;
            accv.z += ws * v4.z; accv.w += ws * v4.w;
        }
        sred4[tid] = accv;
        __syncthreads();
        if (tid < 16) {
            float4 t = make_float4(0.f, 0.f, 0.f, 0.f);
            #pragma unroll
            for (int s = 0; s < 8; s++) {
                float4 v = sred4[s * 16 + tid];
                t.x += v.x; t.y += v.y; t.z += v.z; t.w += v.w;
            }
            *(float4*)&mix[((size_t)(b * LQ_ + qi)) * (HH * DVV) + h * 64 + tid * 4] = t;
        }
    }
}

// ---------------------------------------------------------------------------
extern "C" void kernel_launch(void* const* d_in, const int* in_sizes, int n_in,
                              void* d_out, int out_size) {
    (void)in_sizes; (void)n_in;
    const float* q    = (const float*)d_in[0];
    const float* k    = (const float*)d_in[1];
    const float* v    = (const float*)d_in[2];
    const float* w_qs = (const float*)d_in[3];
    const float* w_ks = (const float*)d_in[4];
    const float* w_vs = (const float*)d_in[5];
    const float* fc   = (const float*)d_in[6];
    float* out = (float*)d_out;

    float *qp, *kp, *vp, *mix, *lg;
    cudaGetSymbolAddress((void**)&qp,  g_qp);
    cudaGetSymbolAddress((void**)&kp,  g_kp);
    cudaGetSymbolAddress((void**)&vp,  g_vp);
    cudaGetSymbolAddress((void**)&mix, g_mix);
    cudaGetSymbolAddress((void**)&lg,  g_logits);

    const long long out_elems  = (long long)BB * LQ_ * DVV;           // 262144
    const long long attn_elems = (long long)BB * HH * LQ_ * LK_;      // 134217728
    int write_attn = ((long long)out_size >= out_elems + attn_elems) ? 1 : 0;
    float* attn = out + out_elems;

    // launch 0: merged QP/KP/VP projections (z-batched, K-tile 8 proven core)
    ProjArgs pa;
    pa.A[0] = q;    pa.W[0] = w_qs; pa.C[0] = qp; pa.K[0] = EE;  pa.scale[0] = 0.125f;
    pa.A[1] = k;    pa.W[1] = w_ks; pa.C[1] = kp; pa.K[1] = EE;  pa.scale[1] = 1.0f;
    pa.A[2] = v;    pa.W[2] = w_vs; pa.C[2] = vp; pa.K[2] = DVV; pa.scale[2] = 1.0f;
    proj_gemm<<<dim3(8, 32, 3), 128>>>(pa);

    // launch 1: logits[bh] = QP[bh] @ KP[bh]^T (K=64 single-shot smem)
    sgemm_logits<<<dim3(16, 16, BB*HH), 128>>>(qp, kp, lg,
                                               (size_t)LQ_ * DKK, (size_t)LK_ * DKK,
                                               (size_t)LQ_ * LK_);

    // launch 2: noop so the ncu capture window (index 3) lands on topk
    noop_kernel<<<1, 32>>>();

    // launch 3: top-k + softmax + AV + attn   <-- ncu window
    topk_attn_kernel<<<BB * HH * LQ_, 128>>>(lg, vp, mix, attn, write_attn);

    // launch 4: out = mix @ fc^T
    sgemm_fc<<<dim3(1, 128), 256>>>(mix, fc, out, BB*LQ_, DVV, HH*DVV);
}